// round 13
// baseline (speedup 1.0000x reference)
#include <cuda_runtime.h>
#include <cuda_fp16.h>
#include <cstdint>

#define Td 4
#define Bd 32
#define Cd 384
#define HWd 256
#define NTOT 32768          // Td*Bd*HWd
#define HEADS 8
#define CHD 48
#define EPSB 1e-5f
#define NELEM 12582912      // Td*Bd*Cd*HWd
#define WSC 16384.0f
#define WSCI 6.103515625e-05f   // 1/16384

#define ASTG 20480          // qkv A stage: 2 terms * 128 rows * 40 halves * 2B
#define BSTG 16896          // B stage: 32 rows * 264 halves * 2B
#define STG  (ASTG + BSTG)  // 37376
#define DSMEM (4 * STG)     // 149504

#define ASTG_P 10240        // proj A stage: 1 term
#define STG_P (ASTG_P + BSTG)   // 27136
#define DSMEM_P (4 * STG_P)     // 108544

// ---- scratch ----
__device__ __half g_sx[Cd * NTOT];            // shortcut-LIF spikes [c][(t*B+b)*HW+n]
__device__ __half g_sqkv[3 * Cd * NTOT];      // q,k,v spikes (rows 0..1151)
__device__ __half g_kvs[Td * Bd * Cd];        // talking-heads spikes [tb][c]
__device__ __half g_w[2][4 * Cd][Cd];         // 2-term fp16 split weights (x16384)
__device__ float  g_scale[4 * Cd];
__device__ float  g_bias[4 * Cd];

// ---------------------------------------------------------------------------
__device__ __forceinline__ uint32_t cvta_smem(const void* p) {
    uint32_t a;
    asm("{ .reg .u64 t; cvta.to.shared.u64 t, %1; cvt.u32.u64 %0, t; }" : "=r"(a) : "l"(p));
    return a;
}
__device__ __forceinline__ void cp16(uint32_t d, const void* s) {
    asm volatile("cp.async.cg.shared.global [%0], [%1], 16;" :: "r"(d), "l"(s));
}
__device__ __forceinline__ void cp_commit() {
    asm volatile("cp.async.commit_group;" ::: "memory");
}
template <int N>
__device__ __forceinline__ void cp_wait() {
    asm volatile("cp.async.wait_group %0;" :: "n"(N) : "memory");
}
__device__ __forceinline__ void ldsm_x4(uint32_t* r, uint32_t a) {
    asm volatile("ldmatrix.sync.aligned.m8n8.x4.shared.b16 {%0,%1,%2,%3},[%4];"
                 : "=r"(r[0]), "=r"(r[1]), "=r"(r[2]), "=r"(r[3]) : "r"(a));
}
__device__ __forceinline__ void ldsm_x4t(uint32_t& r0, uint32_t& r1, uint32_t& r2, uint32_t& r3, uint32_t a) {
    asm volatile("ldmatrix.sync.aligned.m8n8.x4.trans.shared.b16 {%0,%1,%2,%3},[%4];"
                 : "=r"(r0), "=r"(r1), "=r"(r2), "=r"(r3) : "r"(a));
}
__device__ __forceinline__ void mma_f16(float* d, const uint32_t* a, const uint32_t* b) {
    asm volatile("mma.sync.aligned.m16n8k16.row.col.f32.f16.f16.f32 "
                 "{%0,%1,%2,%3},{%4,%5,%6,%7},{%8,%9},{%0,%1,%2,%3};"
                 : "+f"(d[0]), "+f"(d[1]), "+f"(d[2]), "+f"(d[3])
                 : "r"(a[0]), "r"(a[1]), "r"(a[2]), "r"(a[3]), "r"(b[0]), "r"(b[1]));
}

// ---------------------------------------------------------------------------
// wsplit (+ prep folded into the extra tail block)
// ---------------------------------------------------------------------------
__global__ void wsplit_prep_kernel(
    const float* qw, const float* kw, const float* vw, const float* pw,
    const float* qg, const float* qb, const float* qm, const float* qv,
    const float* kg, const float* kb, const float* km, const float* kvv,
    const float* vg, const float* vb, const float* vm, const float* vvv,
    const float* pb, const float* pg, const float* pbe, const float* pm, const float* pv)
{
    if (blockIdx.x == 2304) {                       // prep block
        for (int d = threadIdx.x; d < Cd; d += 256) {
            float s;
            s = qg[d] * rsqrtf(qv[d] + EPSB);  g_scale[d]        = s; g_bias[d]        = qb[d] - qm[d] * s;
            s = kg[d] * rsqrtf(kvv[d] + EPSB); g_scale[Cd + d]   = s; g_bias[Cd + d]   = kb[d] - km[d] * s;
            s = vg[d] * rsqrtf(vvv[d] + EPSB); g_scale[2*Cd + d] = s; g_bias[2*Cd + d] = vb[d] - vm[d] * s;
            s = pg[d] * rsqrtf(pv[d] + EPSB);  g_scale[3*Cd + d] = s; g_bias[3*Cd + d] = (pb[d] - pm[d]) * s + pbe[d];
        }
        return;
    }
    int tid = blockIdx.x * 256 + threadIdx.x;      // 1536*384 exact
    int row = tid / Cd, cin = tid - row * Cd;
    const float* src = (row < Cd) ? qw : (row < 2*Cd) ? kw : (row < 3*Cd) ? vw : pw;
    float a = src[(row % Cd) * Cd + cin] * WSC;
    __half h1 = __float2half_rn(a);
    float r1 = a - __half2float(h1);
    g_w[0][row][cin] = h1;
    g_w[1][row][cin] = __float2half_rn(r1);
}

// ---------------------------------------------------------------------------
__global__ void lif_x_kernel(const float* __restrict__ x)
{
    int tid = blockIdx.x * 256 + threadIdx.x;      // Bd*Cd*HWd exact
    int n = tid % HWd;
    int c = (tid / HWd) % Cd;
    int b = tid / (HWd * Cd);
    float v = 0.f;
#pragma unroll
    for (int t = 0; t < Td; t++) {
        float xv = x[(size_t)((t * Bd + b) * Cd + c) * HWd + n];
        v = 0.5f * (v + xv);
        float s = (v >= 1.0f) ? 1.f : 0.f;
        v *= (1.f - s);
        g_sx[(size_t)c * NTOT + (size_t)(t * Bd + b) * HWd + n] = __float2half(s);
    }
}

// ---------------------------------------------------------------------------
// qkv GEMM (R12 config + row_base): block 128(M) x 256(N=64n x 4t) x 32(K),
// warps 2x4, warp tile 64x64, 4-stage cp.async, hoisted A fragments.
// Epilogue: temporal LIF -> spikes.
// ---------------------------------------------------------------------------
__global__ void __launch_bounds__(256) mma_gemm_qkv(const __half* __restrict__ Bmat,
                                                    int row_base)
{
    extern __shared__ char dsm[];
    const uint32_t sb = cvta_smem(dsm);

    const int tid = threadIdx.x;
    const int warp = tid >> 5, lane = tid & 31;
    const int wm0 = (warp >> 2) * 64, wn0 = (warp & 3) * 64;
    const int m_blk = row_base + blockIdx.y * 128;
    const int b  = blockIdx.x >> 2;
    const int n0 = (blockIdx.x & 3) * 64;

    float acc[4][8][4];
#pragma unroll
    for (int i = 0; i < 4; i++)
#pragma unroll
        for (int j = 0; j < 8; j++)
#pragma unroll
            for (int r = 0; r < 4; r++) acc[i][j][r] = 0.f;

    auto issue = [&](int ch) {
        const uint32_t stg = sb + (ch & 3) * STG;
        const int k0 = ch * 32;
#pragma unroll
        for (int it = 0; it < 4; it++) {          // A
            int o = tid + it * 256;
            int term = o >> 9, rem = o & 511;
            int r = rem >> 2, cq = rem & 3;
            cp16(stg + term * 10240 + r * 80 + cq * 16,
                 &g_w[term][m_blk + r][k0 + cq * 8]);
        }
#pragma unroll
        for (int it = 0; it < 4; it++) {          // B
            int o = tid + it * 256;
            int r = o >> 5, q = o & 31;
            int t = (q >> 1) & 3;
            int n = n0 + (q >> 3) * 16 + (q & 1) * 8;
            cp16(stg + ASTG + r * 528 + q * 16,
                 &Bmat[(size_t)(k0 + r) * NTOT + (size_t)(t * Bd + b) * HWd + n]);
        }
        cp_commit();
    };

    auto compute = [&](int ch) {
        const uint32_t stg = sb + (ch & 3) * STG;
#pragma unroll
        for (int ks = 0; ks < 2; ks++) {
            const int kk = ks * 16;
            uint32_t bfrag[8][2];
#pragma unroll
            for (int h = 0; h < 4; h++) {
                uint32_t r0, r1, r2, r3;
                uint32_t a = stg + ASTG + (kk + (lane & 15)) * 528
                           + (wn0 + h * 16 + (lane >> 4) * 8) * 2;
                ldsm_x4t(r0, r1, r2, r3, a);
                bfrag[h * 2][0] = r0;     bfrag[h * 2][1] = r1;
                bfrag[h * 2 + 1][0] = r2; bfrag[h * 2 + 1][1] = r3;
            }
            uint32_t afr[2][4][4];
#pragma unroll
            for (int term = 0; term < 2; term++)
#pragma unroll
                for (int mt = 0; mt < 4; mt++)
                    ldsm_x4(afr[term][mt],
                            stg + term * 10240
                            + (wm0 + mt * 16 + (lane & 15)) * 80
                            + (kk + (lane >> 4) * 8) * 2);
#pragma unroll
            for (int term = 0; term < 2; term++)
#pragma unroll
                for (int mt = 0; mt < 4; mt++)
#pragma unroll
                    for (int nt = 0; nt < 8; nt++)
                        mma_f16(acc[mt][nt], afr[term][mt], bfrag[nt]);
        }
    };

    issue(0); issue(1); issue(2);
#pragma unroll
    for (int ch = 0; ch < 12; ch++) {
        int rem = 11 - ch;
        if (rem >= 2) cp_wait<2>(); else if (rem == 1) cp_wait<1>(); else cp_wait<0>();
        __syncthreads();
        if (ch + 3 < 12) issue(ch + 3);
        compute(ch);
    }

    const int g = lane >> 2, tig = lane & 3;
#pragma unroll
    for (int mt = 0; mt < 4; mt++) {
#pragma unroll
        for (int i = 0; i < 2; i++) {
            int row = m_blk + wm0 + mt * 16 + g + i * 8;
            float sc = g_scale[row] * WSCI;
            float bi = g_bias[row];
#pragma unroll
            for (int r = 0; r < 2; r++) {
#pragma unroll
                for (int j = 0; j < 2; j++) {
                    int n = n0 + (warp & 3) * 16 + r * 8 + tig * 2 + j;
                    float v = 0.f;
#pragma unroll
                    for (int t = 0; t < Td; t++) {
                        float z = acc[mt][2 * t + r][i * 2 + j] * sc + bi;
                        v = 0.5f * (v + z);
                        float s = (v >= 1.0f) ? 1.f : 0.f;
                        v *= (1.f - s);
                        g_sqkv[(size_t)row * NTOT + (size_t)(t * Bd + b) * HWd + n] =
                            __float2half(s);
                    }
                }
            }
        }
    }
}

// ---------------------------------------------------------------------------
// proj GEMM: single fp16 term, fp32 acc; B = q-spikes of one tb; A * kv.
// Epilogue: scatter (tb,c,n) + identity.
// ---------------------------------------------------------------------------
__global__ void __launch_bounds__(256) mma_gemm_proj(
    const __half* __restrict__ Bmat, float* __restrict__ out,
    const float* __restrict__ identity)
{
    extern __shared__ char dsm[];
    __shared__ __half skv[Cd];
    const uint32_t sb = cvta_smem(dsm);
    const int row_off = 3 * Cd;

    const int tid = threadIdx.x;
    const int warp = tid >> 5, lane = tid & 31;
    const int wm0 = (warp >> 2) * 64, wn0 = (warp & 3) * 64;
    const int m_blk = blockIdx.y * 128;
    const int tb = blockIdx.x;
    const int n_blk = tb * 256;

    for (int i = tid; i < Cd; i += 256) skv[i] = g_kvs[(size_t)tb * Cd + i];

    float acc[4][8][4];
#pragma unroll
    for (int i = 0; i < 4; i++)
#pragma unroll
        for (int j = 0; j < 8; j++)
#pragma unroll
            for (int r = 0; r < 4; r++) acc[i][j][r] = 0.f;

    auto issue = [&](int ch) {
        const uint32_t stg = sb + (ch & 3) * STG_P;
        const int k0 = ch * 32;
#pragma unroll
        for (int it = 0; it < 2; it++) {          // A: 512 cp16
            int o = tid + it * 256;
            int r = o >> 2, cq = o & 3;
            cp16(stg + r * 80 + cq * 16, &g_w[0][row_off + m_blk + r][k0 + cq * 8]);
        }
#pragma unroll
        for (int it = 0; it < 4; it++) {          // B: 1024 cp16
            int o = tid + it * 256;
            int r = o >> 5, q = o & 31;
            cp16(stg + ASTG_P + r * 528 + q * 16,
                 &Bmat[(size_t)(k0 + r) * NTOT + n_blk + q * 8]);
        }
        cp_commit();
    };

    auto compute = [&](int ch) {
        const uint32_t stg = sb + (ch & 3) * STG_P;
        const int k0 = ch * 32;
#pragma unroll
        for (int ks = 0; ks < 2; ks++) {
            const int kk = ks * 16;
            uint32_t bfrag[8][2];
#pragma unroll
            for (int h = 0; h < 4; h++) {
                uint32_t r0, r1, r2, r3;
                uint32_t a = stg + ASTG_P + (kk + (lane & 15)) * 528
                           + (wn0 + h * 16 + (lane >> 4) * 8) * 2;
                ldsm_x4t(r0, r1, r2, r3, a);
                bfrag[h * 2][0] = r0;     bfrag[h * 2][1] = r1;
                bfrag[h * 2 + 1][0] = r2; bfrag[h * 2 + 1][1] = r3;
            }
            uint32_t kvlo = *(const uint32_t*)&skv[k0 + kk + (lane & 3) * 2];
            uint32_t kvhi = *(const uint32_t*)&skv[k0 + kk + 8 + (lane & 3) * 2];
            __half2 lo = *(__half2*)&kvlo, hi = *(__half2*)&kvhi;
            uint32_t afr[4][4];
#pragma unroll
            for (int mt = 0; mt < 4; mt++) {
                ldsm_x4(afr[mt],
                        stg + (wm0 + mt * 16 + (lane & 15)) * 80
                        + (kk + (lane >> 4) * 8) * 2);
                __half2* af = (__half2*)afr[mt];
                af[0] = __hmul2(af[0], lo); af[1] = __hmul2(af[1], lo);
                af[2] = __hmul2(af[2], hi); af[3] = __hmul2(af[3], hi);
            }
#pragma unroll
            for (int mt = 0; mt < 4; mt++)
#pragma unroll
                for (int nt = 0; nt < 8; nt++)
                    mma_f16(acc[mt][nt], afr[mt], bfrag[nt]);
        }
    };

    issue(0); issue(1); issue(2);
#pragma unroll
    for (int ch = 0; ch < 12; ch++) {
        int rem = 11 - ch;
        if (rem >= 2) cp_wait<2>(); else if (rem == 1) cp_wait<1>(); else cp_wait<0>();
        __syncthreads();
        if (ch + 3 < 12) issue(ch + 3);
        compute(ch);
    }

    const int g = lane >> 2, tig = lane & 3;
#pragma unroll
    for (int mt = 0; mt < 4; mt++) {
#pragma unroll
        for (int i = 0; i < 2; i++) {
            int row = m_blk + wm0 + mt * 16 + g + i * 8;
            float sc = g_scale[row_off + row] * WSCI;
            float bi = g_bias[row_off + row];
#pragma unroll
            for (int nt = 0; nt < 8; nt++) {
#pragma unroll
                for (int j = 0; j < 2; j++) {
                    int n = wn0 + nt * 8 + tig * 2 + j;
                    float val = acc[mt][nt][i * 2 + j] * sc + bi;
                    size_t oi = ((size_t)tb * Cd + row) * HWd + n;
                    out[oi] = val + identity[oi];
                }
            }
        }
    }
}

// ---------------------------------------------------------------------------
__global__ void kv_kernel()
{
    int bc = blockIdx.x;
    int c = bc % Cd, b = bc / Cd;
    int n = threadIdx.x;
    float p[Td];
#pragma unroll
    for (int t = 0; t < Td; t++) {
        size_t o = (size_t)(t * Bd + b) * HWd + n;
        float kk = __half2float(g_sqkv[(size_t)(Cd + c) * NTOT + o]);
        float vv = __half2float(g_sqkv[(size_t)(2 * Cd + c) * NTOT + o]);
        p[t] = kk * vv;
    }
#pragma unroll
    for (int t = 0; t < Td; t++)
        for (int o = 16; o > 0; o >>= 1) p[t] += __shfl_down_sync(0xffffffffu, p[t], o);
    __shared__ float wsum[Td][8];
    int lane = n & 31, wid = n >> 5;
    if (lane == 0)
#pragma unroll
        for (int t = 0; t < Td; t++) wsum[t][wid] = p[t];
    __syncthreads();
    if (n == 0) {
        float v = 0.f;
#pragma unroll
        for (int t = 0; t < Td; t++) {
            float kvp = 0.f;
#pragma unroll
            for (int w = 0; w < 8; w++) kvp += wsum[t][w];
            v = 0.5f * (v + kvp);
            float s = (v >= 0.5f) ? 1.f : 0.f;
            v *= (1.f - s);
            g_kvs[(size_t)(t * Bd + b) * Cd + c] = __float2half(s);
        }
    }
}

// ---------------------------------------------------------------------------
__global__ void vout_kernel(float* __restrict__ out2)
{
    __shared__ __half s[CHD][HWd + 8];
    int tb = blockIdx.x, head = blockIdx.y;
    int tid = threadIdx.x;                    // 256
#pragma unroll
    for (int ch = 0; ch < CHD; ch++)
        s[ch][tid] = g_sqkv[(size_t)(2 * Cd + head * CHD + ch) * NTOT
                            + (size_t)tb * HWd + tid];
    __syncthreads();
#pragma unroll
    for (int it = 0; it < CHD; it++) {
        int idx = it * 256 + tid;             // 48*256 elems, contiguous out
        int ch = idx % CHD, n = idx / CHD;
        out2[((size_t)(tb * HEADS + head) * HWd + n) * CHD + ch] =
            __half2float(s[ch][n]);
    }
}

// ---------------------------------------------------------------------------
// side-stream resources: created once on the FIRST (uncaptured) call
struct SideRes {
    cudaStream_t s;
    cudaEvent_t e1, e2;
    SideRes() {
        cudaStreamCreateWithFlags(&s, cudaStreamNonBlocking);
        cudaEventCreateWithFlags(&e1, cudaEventDisableTiming);
        cudaEventCreateWithFlags(&e2, cudaEventDisableTiming);
    }
};

extern "C" void kernel_launch(void* const* d_in, const int* in_sizes, int n_in,
                              void* d_out, int out_size)
{
    const float* x   = (const float*)d_in[0];
    const float* qw  = (const float*)d_in[1];
    const float* qg  = (const float*)d_in[2];
    const float* qb  = (const float*)d_in[3];
    const float* qm  = (const float*)d_in[4];
    const float* qv  = (const float*)d_in[5];
    const float* kw  = (const float*)d_in[6];
    const float* kg  = (const float*)d_in[7];
    const float* kb  = (const float*)d_in[8];
    const float* km  = (const float*)d_in[9];
    const float* kv  = (const float*)d_in[10];
    const float* vw  = (const float*)d_in[11];
    const float* vg  = (const float*)d_in[12];
    const float* vb  = (const float*)d_in[13];
    const float* vm  = (const float*)d_in[14];
    const float* vv  = (const float*)d_in[15];
    const float* pw  = (const float*)d_in[16];
    const float* pb  = (const float*)d_in[17];
    const float* pg  = (const float*)d_in[18];
    const float* pbe = (const float*)d_in[19];
    const float* pm  = (const float*)d_in[20];
    const float* pv  = (const float*)d_in[21];

    static SideRes R;           // first construction happens on the uncaptured call

    cudaFuncSetAttribute(mma_gemm_qkv, cudaFuncAttributeMaxDynamicSharedMemorySize, DSMEM);
    cudaFuncSetAttribute(mma_gemm_proj, cudaFuncAttributeMaxDynamicSharedMemorySize, DSMEM_P);

    __half *p_sx, *p_sq;
    cudaGetSymbolAddress((void**)&p_sx, g_sx);
    cudaGetSymbolAddress((void**)&p_sq, g_sqkv);

    float* out = (float*)d_out;

    wsplit_prep_kernel<<<2305, 256>>>(qw, kw, vw, pw,
                                      qg, qb, qm, qv, kg, kb, km, kv,
                                      vg, vb, vm, vv, pb, pg, pbe, pm, pv);
    lif_x_kernel<<<12288, 256>>>(x);

    // k + v row tiles first (rows 384..1151)
    mma_gemm_qkv<<<dim3(Bd * 4, 6), 256, DSMEM>>>(p_sx, Cd);

    // fork: kv + vout on side stream, q-GEMM on main stream
    cudaEventRecord(R.e1, 0);
    cudaStreamWaitEvent(R.s, R.e1, 0);
    kv_kernel<<<Bd * Cd, 256, 0, R.s>>>();
    if (out_size >= 2 * NELEM)
        vout_kernel<<<dim3(Td * Bd, HEADS), 256, 0, R.s>>>(out + NELEM);

    mma_gemm_qkv<<<dim3(Bd * 4, 3), 256, DSMEM>>>(p_sx, 0);   // q rows

    cudaEventRecord(R.e2, R.s);
    cudaStreamWaitEvent(0, R.e2, 0);

    dim3 g2(Td * Bd, 3);                          // 128 tb x 3 row-tiles
    mma_gemm_proj<<<g2, 256, DSMEM_P>>>(p_sq, out, x);
}

// round 14
// speedup vs baseline: 1.0758x; 1.0758x over previous
#include <cuda_runtime.h>
#include <cuda_fp16.h>
#include <cstdint>

#define Td 4
#define Bd 32
#define Cd 384
#define HWd 256
#define NTOT 32768          // Td*Bd*HWd
#define HEADS 8
#define CHD 48
#define EPSB 1e-5f
#define NELEM 12582912      // Td*Bd*Cd*HWd
#define WSC 16384.0f
#define WSCI 6.103515625e-05f   // 1/16384

#define ASTG 20480          // qkv A stage: 2 terms * 128 rows * 40 halves * 2B
#define BSTG 16896          // B stage: 32 rows * 264 halves * 2B
#define STG  (ASTG + BSTG)  // 37376
#define DSMEM (4 * STG)     // 149504

#define ASTG_P 10240        // proj A stage: 1 term
#define STG_P (ASTG_P + BSTG)   // 27136
#define DSMEM_P (4 * STG_P)     // 108544

// ---- scratch ----
__device__ __half g_sx[Cd * NTOT];            // shortcut-LIF spikes [c][(t*B+b)*HW+n]
__device__ __half g_sqkv[3 * Cd * NTOT];      // q,k,v spikes (rows 0..1151)
__device__ __half g_kvs[Td * Bd * Cd];        // talking-heads spikes [tb][c]
__device__ __half g_w[2][4 * Cd][Cd];         // 2-term fp16 split weights (x16384)
__device__ float  g_scale[4 * Cd];
__device__ float  g_bias[4 * Cd];

// ---------------------------------------------------------------------------
__device__ __forceinline__ uint32_t cvta_smem(const void* p) {
    uint32_t a;
    asm("{ .reg .u64 t; cvta.to.shared.u64 t, %1; cvt.u32.u64 %0, t; }" : "=r"(a) : "l"(p));
    return a;
}
__device__ __forceinline__ void cp16(uint32_t d, const void* s) {
    asm volatile("cp.async.cg.shared.global [%0], [%1], 16;" :: "r"(d), "l"(s));
}
__device__ __forceinline__ void cp_commit() {
    asm volatile("cp.async.commit_group;" ::: "memory");
}
template <int N>
__device__ __forceinline__ void cp_wait() {
    asm volatile("cp.async.wait_group %0;" :: "n"(N) : "memory");
}
__device__ __forceinline__ void ldsm_x4(uint32_t* r, uint32_t a) {
    asm volatile("ldmatrix.sync.aligned.m8n8.x4.shared.b16 {%0,%1,%2,%3},[%4];"
                 : "=r"(r[0]), "=r"(r[1]), "=r"(r[2]), "=r"(r[3]) : "r"(a));
}
__device__ __forceinline__ void ldsm_x4t(uint32_t& r0, uint32_t& r1, uint32_t& r2, uint32_t& r3, uint32_t a) {
    asm volatile("ldmatrix.sync.aligned.m8n8.x4.trans.shared.b16 {%0,%1,%2,%3},[%4];"
                 : "=r"(r0), "=r"(r1), "=r"(r2), "=r"(r3) : "r"(a));
}
__device__ __forceinline__ void mma_f16(float* d, const uint32_t* a, const uint32_t* b) {
    asm volatile("mma.sync.aligned.m16n8k16.row.col.f32.f16.f16.f32 "
                 "{%0,%1,%2,%3},{%4,%5,%6,%7},{%8,%9},{%0,%1,%2,%3};"
                 : "+f"(d[0]), "+f"(d[1]), "+f"(d[2]), "+f"(d[3])
                 : "r"(a[0]), "r"(a[1]), "r"(a[2]), "r"(a[3]), "r"(b[0]), "r"(b[1]));
}

// ---------------------------------------------------------------------------
// wsplit + BN prep (prep folded into the extra tail block)
// ---------------------------------------------------------------------------
__global__ void wsplit_prep_kernel(
    const float* qw, const float* kw, const float* vw, const float* pw,
    const float* qg, const float* qb, const float* qm, const float* qv,
    const float* kg, const float* kb, const float* km, const float* kvv,
    const float* vg, const float* vb, const float* vm, const float* vvv,
    const float* pb, const float* pg, const float* pbe, const float* pm, const float* pv)
{
    if (blockIdx.x == 2304) {                       // prep block
        for (int d = threadIdx.x; d < Cd; d += 256) {
            float s;
            s = qg[d] * rsqrtf(qv[d] + EPSB);  g_scale[d]        = s; g_bias[d]        = qb[d] - qm[d] * s;
            s = kg[d] * rsqrtf(kvv[d] + EPSB); g_scale[Cd + d]   = s; g_bias[Cd + d]   = kb[d] - km[d] * s;
            s = vg[d] * rsqrtf(vvv[d] + EPSB); g_scale[2*Cd + d] = s; g_bias[2*Cd + d] = vb[d] - vm[d] * s;
            s = pg[d] * rsqrtf(pv[d] + EPSB);  g_scale[3*Cd + d] = s; g_bias[3*Cd + d] = (pb[d] - pm[d]) * s + pbe[d];
        }
        return;
    }
    int tid = blockIdx.x * 256 + threadIdx.x;      // 1536*384 exact
    int row = tid / Cd, cin = tid - row * Cd;
    const float* src = (row < Cd) ? qw : (row < 2*Cd) ? kw : (row < 3*Cd) ? vw : pw;
    float a = src[(row % Cd) * Cd + cin] * WSC;
    __half h1 = __float2half_rn(a);
    float r1 = a - __half2float(h1);
    g_w[0][row][cin] = h1;
    g_w[1][row][cin] = __float2half_rn(r1);
}

// ---------------------------------------------------------------------------
__global__ void lif_x_kernel(const float* __restrict__ x)
{
    int tid = blockIdx.x * 256 + threadIdx.x;      // Bd*Cd*HWd exact
    int n = tid % HWd;
    int c = (tid / HWd) % Cd;
    int b = tid / (HWd * Cd);
    float v = 0.f;
#pragma unroll
    for (int t = 0; t < Td; t++) {
        float xv = x[(size_t)((t * Bd + b) * Cd + c) * HWd + n];
        v = 0.5f * (v + xv);
        float s = (v >= 1.0f) ? 1.f : 0.f;
        v *= (1.f - s);
        g_sx[(size_t)c * NTOT + (size_t)(t * Bd + b) * HWd + n] = __float2half(s);
    }
}

// ---------------------------------------------------------------------------
// qkv GEMM (R12 config): block 128(M) x 256(N=64n x 4t) x 32(K), warps 2x4,
// warp tile 64x64, 4-stage cp.async, hoisted A fragments. Epilogue: LIF.
// ---------------------------------------------------------------------------
__global__ void __launch_bounds__(256) mma_gemm_qkv(const __half* __restrict__ Bmat)
{
    extern __shared__ char dsm[];
    const uint32_t sb = cvta_smem(dsm);

    const int tid = threadIdx.x;
    const int warp = tid >> 5, lane = tid & 31;
    const int wm0 = (warp >> 2) * 64, wn0 = (warp & 3) * 64;
    const int m_blk = blockIdx.y * 128;
    const int b  = blockIdx.x >> 2;
    const int n0 = (blockIdx.x & 3) * 64;

    float acc[4][8][4];
#pragma unroll
    for (int i = 0; i < 4; i++)
#pragma unroll
        for (int j = 0; j < 8; j++)
#pragma unroll
            for (int r = 0; r < 4; r++) acc[i][j][r] = 0.f;

    auto issue = [&](int ch) {
        const uint32_t stg = sb + (ch & 3) * STG;
        const int k0 = ch * 32;
#pragma unroll
        for (int it = 0; it < 4; it++) {          // A
            int o = tid + it * 256;
            int term = o >> 9, rem = o & 511;
            int r = rem >> 2, cq = rem & 3;
            cp16(stg + term * 10240 + r * 80 + cq * 16,
                 &g_w[term][m_blk + r][k0 + cq * 8]);
        }
#pragma unroll
        for (int it = 0; it < 4; it++) {          // B
            int o = tid + it * 256;
            int r = o >> 5, q = o & 31;
            int t = (q >> 1) & 3;
            int n = n0 + (q >> 3) * 16 + (q & 1) * 8;
            cp16(stg + ASTG + r * 528 + q * 16,
                 &Bmat[(size_t)(k0 + r) * NTOT + (size_t)(t * Bd + b) * HWd + n]);
        }
        cp_commit();
    };

    auto compute = [&](int ch) {
        const uint32_t stg = sb + (ch & 3) * STG;
#pragma unroll
        for (int ks = 0; ks < 2; ks++) {
            const int kk = ks * 16;
            uint32_t bfrag[8][2];
#pragma unroll
            for (int h = 0; h < 4; h++) {
                uint32_t r0, r1, r2, r3;
                uint32_t a = stg + ASTG + (kk + (lane & 15)) * 528
                           + (wn0 + h * 16 + (lane >> 4) * 8) * 2;
                ldsm_x4t(r0, r1, r2, r3, a);
                bfrag[h * 2][0] = r0;     bfrag[h * 2][1] = r1;
                bfrag[h * 2 + 1][0] = r2; bfrag[h * 2 + 1][1] = r3;
            }
            uint32_t afr[2][4][4];
#pragma unroll
            for (int term = 0; term < 2; term++)
#pragma unroll
                for (int mt = 0; mt < 4; mt++)
                    ldsm_x4(afr[term][mt],
                            stg + term * 10240
                            + (wm0 + mt * 16 + (lane & 15)) * 80
                            + (kk + (lane >> 4) * 8) * 2);
#pragma unroll
            for (int term = 0; term < 2; term++)
#pragma unroll
                for (int mt = 0; mt < 4; mt++)
#pragma unroll
                    for (int nt = 0; nt < 8; nt++)
                        mma_f16(acc[mt][nt], afr[term][mt], bfrag[nt]);
        }
    };

    issue(0); issue(1); issue(2);
#pragma unroll
    for (int ch = 0; ch < 12; ch++) {
        int rem = 11 - ch;
        if (rem >= 2) cp_wait<2>(); else if (rem == 1) cp_wait<1>(); else cp_wait<0>();
        __syncthreads();
        if (ch + 3 < 12) issue(ch + 3);
        compute(ch);
    }

    const int g = lane >> 2, tig = lane & 3;
#pragma unroll
    for (int mt = 0; mt < 4; mt++) {
#pragma unroll
        for (int i = 0; i < 2; i++) {
            int row = m_blk + wm0 + mt * 16 + g + i * 8;
            float sc = g_scale[row] * WSCI;
            float bi = g_bias[row];
#pragma unroll
            for (int r = 0; r < 2; r++) {
#pragma unroll
                for (int j = 0; j < 2; j++) {
                    int n = n0 + (warp & 3) * 16 + r * 8 + tig * 2 + j;
                    float v = 0.f;
#pragma unroll
                    for (int t = 0; t < Td; t++) {
                        float z = acc[mt][2 * t + r][i * 2 + j] * sc + bi;
                        v = 0.5f * (v + z);
                        float s = (v >= 1.0f) ? 1.f : 0.f;
                        v *= (1.f - s);
                        g_sqkv[(size_t)row * NTOT + (size_t)(t * Bd + b) * HWd + n] =
                            __float2half(s);
                    }
                }
            }
        }
    }
}

// ---------------------------------------------------------------------------
// proj GEMM: single fp16 term, fp32 acc; B = q-spikes of one tb; A * kv.
// Epilogue: scatter (tb,c,n) + identity.
// ---------------------------------------------------------------------------
__global__ void __launch_bounds__(256) mma_gemm_proj(
    const __half* __restrict__ Bmat, float* __restrict__ out,
    const float* __restrict__ identity)
{
    extern __shared__ char dsm[];
    __shared__ __half skv[Cd];
    const uint32_t sb = cvta_smem(dsm);
    const int row_off = 3 * Cd;

    const int tid = threadIdx.x;
    const int warp = tid >> 5, lane = tid & 31;
    const int wm0 = (warp >> 2) * 64, wn0 = (warp & 3) * 64;
    const int m_blk = blockIdx.y * 128;
    const int tb = blockIdx.x;
    const int n_blk = tb * 256;

    for (int i = tid; i < Cd; i += 256) skv[i] = g_kvs[(size_t)tb * Cd + i];

    float acc[4][8][4];
#pragma unroll
    for (int i = 0; i < 4; i++)
#pragma unroll
        for (int j = 0; j < 8; j++)
#pragma unroll
            for (int r = 0; r < 4; r++) acc[i][j][r] = 0.f;

    auto issue = [&](int ch) {
        const uint32_t stg = sb + (ch & 3) * STG_P;
        const int k0 = ch * 32;
#pragma unroll
        for (int it = 0; it < 2; it++) {          // A: 512 cp16
            int o = tid + it * 256;
            int r = o >> 2, cq = o & 3;
            cp16(stg + r * 80 + cq * 16, &g_w[0][row_off + m_blk + r][k0 + cq * 8]);
        }
#pragma unroll
        for (int it = 0; it < 4; it++) {          // B: 1024 cp16
            int o = tid + it * 256;
            int r = o >> 5, q = o & 31;
            cp16(stg + ASTG_P + r * 528 + q * 16,
                 &Bmat[(size_t)(k0 + r) * NTOT + n_blk + q * 8]);
        }
        cp_commit();
    };

    auto compute = [&](int ch) {
        const uint32_t stg = sb + (ch & 3) * STG_P;
        const int k0 = ch * 32;
#pragma unroll
        for (int ks = 0; ks < 2; ks++) {
            const int kk = ks * 16;
            uint32_t bfrag[8][2];
#pragma unroll
            for (int h = 0; h < 4; h++) {
                uint32_t r0, r1, r2, r3;
                uint32_t a = stg + ASTG_P + (kk + (lane & 15)) * 528
                           + (wn0 + h * 16 + (lane >> 4) * 8) * 2;
                ldsm_x4t(r0, r1, r2, r3, a);
                bfrag[h * 2][0] = r0;     bfrag[h * 2][1] = r1;
                bfrag[h * 2 + 1][0] = r2; bfrag[h * 2 + 1][1] = r3;
            }
            uint32_t kvlo = *(const uint32_t*)&skv[k0 + kk + (lane & 3) * 2];
            uint32_t kvhi = *(const uint32_t*)&skv[k0 + kk + 8 + (lane & 3) * 2];
            __half2 lo = *(__half2*)&kvlo, hi = *(__half2*)&kvhi;
            uint32_t afr[4][4];
#pragma unroll
            for (int mt = 0; mt < 4; mt++) {
                ldsm_x4(afr[mt],
                        stg + (wm0 + mt * 16 + (lane & 15)) * 80
                        + (kk + (lane >> 4) * 8) * 2);
                __half2* af = (__half2*)afr[mt];
                af[0] = __hmul2(af[0], lo); af[1] = __hmul2(af[1], lo);
                af[2] = __hmul2(af[2], hi); af[3] = __hmul2(af[3], hi);
            }
#pragma unroll
            for (int mt = 0; mt < 4; mt++)
#pragma unroll
                for (int nt = 0; nt < 8; nt++)
                    mma_f16(acc[mt][nt], afr[mt], bfrag[nt]);
        }
    };

    issue(0); issue(1); issue(2);
#pragma unroll
    for (int ch = 0; ch < 12; ch++) {
        int rem = 11 - ch;
        if (rem >= 2) cp_wait<2>(); else if (rem == 1) cp_wait<1>(); else cp_wait<0>();
        __syncthreads();
        if (ch + 3 < 12) issue(ch + 3);
        compute(ch);
    }

    const int g = lane >> 2, tig = lane & 3;
#pragma unroll
    for (int mt = 0; mt < 4; mt++) {
#pragma unroll
        for (int i = 0; i < 2; i++) {
            int row = m_blk + wm0 + mt * 16 + g + i * 8;
            float sc = g_scale[row_off + row] * WSCI;
            float bi = g_bias[row_off + row];
#pragma unroll
            for (int nt = 0; nt < 8; nt++) {
#pragma unroll
                for (int j = 0; j < 2; j++) {
                    int n = wn0 + nt * 8 + tig * 2 + j;
                    float val = acc[mt][nt][i * 2 + j] * sc + bi;
                    size_t oi = ((size_t)tb * Cd + row) * HWd + n;
                    out[oi] = val + identity[oi];
                }
            }
        }
    }
}

// ---------------------------------------------------------------------------
// kv = lif( sum_n k*v , v_th=0.5 ): block per (b,c), 128 threads, half2 loads
// ---------------------------------------------------------------------------
__global__ void kv_kernel()
{
    int bc = blockIdx.x;
    int c = bc % Cd, b = bc / Cd;
    int i = threadIdx.x;                           // 0..127, n = 2i, 2i+1
    float p[Td];
#pragma unroll
    for (int t = 0; t < Td; t++) {
        size_t o = (size_t)(t * Bd + b) * HWd + 2 * i;
        __half2 kk = *(const __half2*)&g_sqkv[(size_t)(Cd + c) * NTOT + o];
        __half2 vv = *(const __half2*)&g_sqkv[(size_t)(2 * Cd + c) * NTOT + o];
        __half2 pr = __hmul2(kk, vv);
        p[t] = __low2float(pr) + __high2float(pr);
    }
#pragma unroll
    for (int t = 0; t < Td; t++)
        for (int o = 16; o > 0; o >>= 1) p[t] += __shfl_down_sync(0xffffffffu, p[t], o);
    __shared__ float wsum[Td][4];
    int lane = i & 31, wid = i >> 5;
    if (lane == 0)
#pragma unroll
        for (int t = 0; t < Td; t++) wsum[t][wid] = p[t];
    __syncthreads();
    if (i == 0) {
        float v = 0.f;
#pragma unroll
        for (int t = 0; t < Td; t++) {
            float kvp = wsum[t][0] + wsum[t][1] + wsum[t][2] + wsum[t][3];
            v = 0.5f * (v + kvp);
            float s = (v >= 0.5f) ? 1.f : 0.f;
            v *= (1.f - s);
            g_kvs[(size_t)(t * Bd + b) * Cd + c] = __float2half(s);
        }
    }
}

// ---------------------------------------------------------------------------
__global__ void vout_kernel(float* __restrict__ out2)
{
    __shared__ __half s[CHD][HWd + 8];
    int tb = blockIdx.x, head = blockIdx.y;
    int tid = threadIdx.x;                    // 256
#pragma unroll
    for (int ch = 0; ch < CHD; ch++)
        s[ch][tid] = g_sqkv[(size_t)(2 * Cd + head * CHD + ch) * NTOT
                            + (size_t)tb * HWd + tid];
    __syncthreads();
#pragma unroll
    for (int it = 0; it < CHD; it++) {
        int idx = it * 256 + tid;             // 48*256 elems, contiguous out
        int ch = idx % CHD, n = idx / CHD;
        out2[((size_t)(tb * HEADS + head) * HWd + n) * CHD + ch] =
            __half2float(s[ch][n]);
    }
}

// ---------------------------------------------------------------------------
// side-stream resources: created once on the FIRST (uncaptured) call
struct SideRes {
    cudaStream_t s;
    cudaEvent_t e0, eW, e1, eV;
    SideRes() {
        cudaStreamCreateWithFlags(&s, cudaStreamNonBlocking);
        cudaEventCreateWithFlags(&e0, cudaEventDisableTiming);
        cudaEventCreateWithFlags(&eW, cudaEventDisableTiming);
        cudaEventCreateWithFlags(&e1, cudaEventDisableTiming);
        cudaEventCreateWithFlags(&eV, cudaEventDisableTiming);
    }
};

extern "C" void kernel_launch(void* const* d_in, const int* in_sizes, int n_in,
                              void* d_out, int out_size)
{
    const float* x   = (const float*)d_in[0];
    const float* qw  = (const float*)d_in[1];
    const float* qg  = (const float*)d_in[2];
    const float* qb  = (const float*)d_in[3];
    const float* qm  = (const float*)d_in[4];
    const float* qv  = (const float*)d_in[5];
    const float* kw  = (const float*)d_in[6];
    const float* kg  = (const float*)d_in[7];
    const float* kb  = (const float*)d_in[8];
    const float* km  = (const float*)d_in[9];
    const float* kv  = (const float*)d_in[10];
    const float* vw  = (const float*)d_in[11];
    const float* vg  = (const float*)d_in[12];
    const float* vb  = (const float*)d_in[13];
    const float* vm  = (const float*)d_in[14];
    const float* vv  = (const float*)d_in[15];
    const float* pw  = (const float*)d_in[16];
    const float* pb  = (const float*)d_in[17];
    const float* pg  = (const float*)d_in[18];
    const float* pbe = (const float*)d_in[19];
    const float* pm  = (const float*)d_in[20];
    const float* pv  = (const float*)d_in[21];

    static SideRes R;           // constructed on the uncaptured correctness call

    cudaFuncSetAttribute(mma_gemm_qkv, cudaFuncAttributeMaxDynamicSharedMemorySize, DSMEM);
    cudaFuncSetAttribute(mma_gemm_proj, cudaFuncAttributeMaxDynamicSharedMemorySize, DSMEM_P);

    __half *p_sx, *p_sq;
    cudaGetSymbolAddress((void**)&p_sx, g_sx);
    cudaGetSymbolAddress((void**)&p_sq, g_sqkv);

    float* out = (float*)d_out;

    // fork 1: weight split on side stream, lif_x on main
    cudaEventRecord(R.e0, 0);
    cudaStreamWaitEvent(R.s, R.e0, 0);
    wsplit_prep_kernel<<<2305, 256, 0, R.s>>>(qw, kw, vw, pw,
                                              qg, qb, qm, qv, kg, kb, km, kv,
                                              vg, vb, vm, vv, pb, pg, pbe, pm, pv);
    cudaEventRecord(R.eW, R.s);

    lif_x_kernel<<<12288, 256>>>(x);
    cudaStreamWaitEvent(0, R.eW, 0);               // join before qkv

    dim3 g1(Bd * 4, 9);                            // full qkv, single launch
    mma_gemm_qkv<<<g1, 256, DSMEM>>>(p_sx);

    // fork 2: vout on side, kv on main; join before proj
    cudaEventRecord(R.e1, 0);
    cudaStreamWaitEvent(R.s, R.e1, 0);
    if (out_size >= 2 * NELEM)
        vout_kernel<<<dim3(Td * Bd, HEADS), 256, 0, R.s>>>(out + NELEM);
    cudaEventRecord(R.eV, R.s);

    kv_kernel<<<Bd * Cd, 128>>>();
    cudaStreamWaitEvent(0, R.eV, 0);               // join before proj

    dim3 g2(Td * Bd, 3);                           // 128 tb x 3 row-tiles
    mma_gemm_proj<<<g2, 256, DSMEM_P>>>(p_sq, out, x);
}

// round 15
// speedup vs baseline: 1.0848x; 1.0084x over previous
#include <cuda_runtime.h>
#include <cuda_fp16.h>
#include <cstdint>

#define Td 4
#define Bd 32
#define Cd 384
#define HWd 256
#define NTOT 32768          // Td*Bd*HWd
#define HEADS 8
#define CHD 48
#define EPSB 1e-5f
#define NELEM 12582912      // Td*Bd*Cd*HWd
#define WSC 16384.0f
#define WSCI 6.103515625e-05f   // 1/16384

#define ASTG 20480          // qkv A stage: 2 terms * 128 rows * 40 halves * 2B
#define BSTG 16896          // B stage: 32 rows * 264 halves * 2B
#define STG  (ASTG + BSTG)  // 37376
#define DSMEM (4 * STG)     // 149504

#define ASTG_P 10240        // proj A stage: 1 term
#define STG_P (ASTG_P + BSTG)   // 27136
#define DSMEM_P (4 * STG_P)     // 108544

// ---- scratch ----
__device__ __half g_sx[Cd * NTOT];            // shortcut-LIF spikes [c][(t*B+b)*HW+n]
__device__ __half g_sqkv[3 * Cd * NTOT];      // q,k,v spikes (rows 0..1151)
__device__ __half g_kvs[Td * Bd * Cd];        // talking-heads spikes [tb][c]
__device__ __half g_w[2][4 * Cd][Cd];         // 2-term fp16 split weights (x16384)
__device__ float  g_scale[4 * Cd];
__device__ float  g_bias[4 * Cd];

// ---------------------------------------------------------------------------
__device__ __forceinline__ uint32_t cvta_smem(const void* p) {
    uint32_t a;
    asm("{ .reg .u64 t; cvta.to.shared.u64 t, %1; cvt.u32.u64 %0, t; }" : "=r"(a) : "l"(p));
    return a;
}
__device__ __forceinline__ void cp16(uint32_t d, const void* s) {
    asm volatile("cp.async.cg.shared.global [%0], [%1], 16;" :: "r"(d), "l"(s));
}
__device__ __forceinline__ void cp_commit() {
    asm volatile("cp.async.commit_group;" ::: "memory");
}
template <int N>
__device__ __forceinline__ void cp_wait() {
    asm volatile("cp.async.wait_group %0;" :: "n"(N) : "memory");
}
__device__ __forceinline__ void ldsm_x4(uint32_t* r, uint32_t a) {
    asm volatile("ldmatrix.sync.aligned.m8n8.x4.shared.b16 {%0,%1,%2,%3},[%4];"
                 : "=r"(r[0]), "=r"(r[1]), "=r"(r[2]), "=r"(r[3]) : "r"(a));
}
__device__ __forceinline__ void ldsm_x4t(uint32_t& r0, uint32_t& r1, uint32_t& r2, uint32_t& r3, uint32_t a) {
    asm volatile("ldmatrix.sync.aligned.m8n8.x4.trans.shared.b16 {%0,%1,%2,%3},[%4];"
                 : "=r"(r0), "=r"(r1), "=r"(r2), "=r"(r3) : "r"(a));
}
__device__ __forceinline__ void mma_f16(float* d, const uint32_t* a, const uint32_t* b) {
    asm volatile("mma.sync.aligned.m16n8k16.row.col.f32.f16.f16.f32 "
                 "{%0,%1,%2,%3},{%4,%5,%6,%7},{%8,%9},{%0,%1,%2,%3};"
                 : "+f"(d[0]), "+f"(d[1]), "+f"(d[2]), "+f"(d[3])
                 : "r"(a[0]), "r"(a[1]), "r"(a[2]), "r"(a[3]), "r"(b[0]), "r"(b[1]));
}

// ---------------------------------------------------------------------------
// wsplit + BN prep (prep folded into the extra tail block)
// ---------------------------------------------------------------------------
__global__ void wsplit_prep_kernel(
    const float* qw, const float* kw, const float* vw, const float* pw,
    const float* qg, const float* qb, const float* qm, const float* qv,
    const float* kg, const float* kb, const float* km, const float* kvv,
    const float* vg, const float* vb, const float* vm, const float* vvv,
    const float* pb, const float* pg, const float* pbe, const float* pm, const float* pv)
{
    if (blockIdx.x == 2304) {                       // prep block
        for (int d = threadIdx.x; d < Cd; d += 256) {
            float s;
            s = qg[d] * rsqrtf(qv[d] + EPSB);  g_scale[d]        = s; g_bias[d]        = qb[d] - qm[d] * s;
            s = kg[d] * rsqrtf(kvv[d] + EPSB); g_scale[Cd + d]   = s; g_bias[Cd + d]   = kb[d] - km[d] * s;
            s = vg[d] * rsqrtf(vvv[d] + EPSB); g_scale[2*Cd + d] = s; g_bias[2*Cd + d] = vb[d] - vm[d] * s;
            s = pg[d] * rsqrtf(pv[d] + EPSB);  g_scale[3*Cd + d] = s; g_bias[3*Cd + d] = (pb[d] - pm[d]) * s + pbe[d];
        }
        return;
    }
    int tid = blockIdx.x * 256 + threadIdx.x;      // 1536*384 exact
    int row = tid / Cd, cin = tid - row * Cd;
    const float* src = (row < Cd) ? qw : (row < 2*Cd) ? kw : (row < 3*Cd) ? vw : pw;
    float a = src[(row % Cd) * Cd + cin] * WSC;
    __half h1 = __float2half_rn(a);
    float r1 = a - __half2float(h1);
    g_w[0][row][cin] = h1;
    g_w[1][row][cin] = __float2half_rn(r1);
}

// ---------------------------------------------------------------------------
__global__ void lif_x_kernel(const float* __restrict__ x)
{
    int tid = blockIdx.x * 256 + threadIdx.x;      // Bd*Cd*HWd exact
    int n = tid % HWd;
    int c = (tid / HWd) % Cd;
    int b = tid / (HWd * Cd);
    float v = 0.f;
#pragma unroll
    for (int t = 0; t < Td; t++) {
        float xv = x[(size_t)((t * Bd + b) * Cd + c) * HWd + n];
        v = 0.5f * (v + xv);
        float s = (v >= 1.0f) ? 1.f : 0.f;
        v *= (1.f - s);
        g_sx[(size_t)c * NTOT + (size_t)(t * Bd + b) * HWd + n] = __float2half(s);
    }
}

// ---------------------------------------------------------------------------
// qkv GEMM (R12 config): block 128(M) x 256(N=64n x 4t) x 32(K), warps 2x4,
// warp tile 64x64, 4-stage cp.async, hoisted A fragments. Epilogue: LIF.
// ---------------------------------------------------------------------------
__global__ void __launch_bounds__(256) mma_gemm_qkv(const __half* __restrict__ Bmat)
{
    extern __shared__ char dsm[];
    const uint32_t sb = cvta_smem(dsm);

    const int tid = threadIdx.x;
    const int warp = tid >> 5, lane = tid & 31;
    const int wm0 = (warp >> 2) * 64, wn0 = (warp & 3) * 64;
    const int m_blk = blockIdx.y * 128;
    const int b  = blockIdx.x >> 2;
    const int n0 = (blockIdx.x & 3) * 64;

    float acc[4][8][4];
#pragma unroll
    for (int i = 0; i < 4; i++)
#pragma unroll
        for (int j = 0; j < 8; j++)
#pragma unroll
            for (int r = 0; r < 4; r++) acc[i][j][r] = 0.f;

    auto issue = [&](int ch) {
        const uint32_t stg = sb + (ch & 3) * STG;
        const int k0 = ch * 32;
#pragma unroll
        for (int it = 0; it < 4; it++) {          // A
            int o = tid + it * 256;
            int term = o >> 9, rem = o & 511;
            int r = rem >> 2, cq = rem & 3;
            cp16(stg + term * 10240 + r * 80 + cq * 16,
                 &g_w[term][m_blk + r][k0 + cq * 8]);
        }
#pragma unroll
        for (int it = 0; it < 4; it++) {          // B
            int o = tid + it * 256;
            int r = o >> 5, q = o & 31;
            int t = (q >> 1) & 3;
            int n = n0 + (q >> 3) * 16 + (q & 1) * 8;
            cp16(stg + ASTG + r * 528 + q * 16,
                 &Bmat[(size_t)(k0 + r) * NTOT + (size_t)(t * Bd + b) * HWd + n]);
        }
        cp_commit();
    };

    auto compute = [&](int ch) {
        const uint32_t stg = sb + (ch & 3) * STG;
#pragma unroll
        for (int ks = 0; ks < 2; ks++) {
            const int kk = ks * 16;
            uint32_t bfrag[8][2];
#pragma unroll
            for (int h = 0; h < 4; h++) {
                uint32_t r0, r1, r2, r3;
                uint32_t a = stg + ASTG + (kk + (lane & 15)) * 528
                           + (wn0 + h * 16 + (lane >> 4) * 8) * 2;
                ldsm_x4t(r0, r1, r2, r3, a);
                bfrag[h * 2][0] = r0;     bfrag[h * 2][1] = r1;
                bfrag[h * 2 + 1][0] = r2; bfrag[h * 2 + 1][1] = r3;
            }
            uint32_t afr[2][4][4];
#pragma unroll
            for (int term = 0; term < 2; term++)
#pragma unroll
                for (int mt = 0; mt < 4; mt++)
                    ldsm_x4(afr[term][mt],
                            stg + term * 10240
                            + (wm0 + mt * 16 + (lane & 15)) * 80
                            + (kk + (lane >> 4) * 8) * 2);
#pragma unroll
            for (int term = 0; term < 2; term++)
#pragma unroll
                for (int mt = 0; mt < 4; mt++)
#pragma unroll
                    for (int nt = 0; nt < 8; nt++)
                        mma_f16(acc[mt][nt], afr[term][mt], bfrag[nt]);
        }
    };

    issue(0); issue(1); issue(2);
#pragma unroll
    for (int ch = 0; ch < 12; ch++) {
        int rem = 11 - ch;
        if (rem >= 2) cp_wait<2>(); else if (rem == 1) cp_wait<1>(); else cp_wait<0>();
        __syncthreads();
        if (ch + 3 < 12) issue(ch + 3);
        compute(ch);
    }

    const int g = lane >> 2, tig = lane & 3;
#pragma unroll
    for (int mt = 0; mt < 4; mt++) {
#pragma unroll
        for (int i = 0; i < 2; i++) {
            int row = m_blk + wm0 + mt * 16 + g + i * 8;
            float sc = g_scale[row] * WSCI;
            float bi = g_bias[row];
#pragma unroll
            for (int r = 0; r < 2; r++) {
#pragma unroll
                for (int j = 0; j < 2; j++) {
                    int n = n0 + (warp & 3) * 16 + r * 8 + tig * 2 + j;
                    float v = 0.f;
#pragma unroll
                    for (int t = 0; t < Td; t++) {
                        float z = acc[mt][2 * t + r][i * 2 + j] * sc + bi;
                        v = 0.5f * (v + z);
                        float s = (v >= 1.0f) ? 1.f : 0.f;
                        v *= (1.f - s);
                        g_sqkv[(size_t)row * NTOT + (size_t)(t * Bd + b) * HWd + n] =
                            __float2half(s);
                    }
                }
            }
        }
    }
}

// ---------------------------------------------------------------------------
// proj GEMM: single fp16 term, fp32 acc; B = q-spikes of one tb; A * kv.
// Epilogue: scatter (tb,c,n) + identity.
// ---------------------------------------------------------------------------
__global__ void __launch_bounds__(256) mma_gemm_proj(
    const __half* __restrict__ Bmat, float* __restrict__ out,
    const float* __restrict__ identity)
{
    extern __shared__ char dsm[];
    __shared__ __half skv[Cd];
    const uint32_t sb = cvta_smem(dsm);
    const int row_off = 3 * Cd;

    const int tid = threadIdx.x;
    const int warp = tid >> 5, lane = tid & 31;
    const int wm0 = (warp >> 2) * 64, wn0 = (warp & 3) * 64;
    const int m_blk = blockIdx.y * 128;
    const int tb = blockIdx.x;
    const int n_blk = tb * 256;

    for (int i = tid; i < Cd; i += 256) skv[i] = g_kvs[(size_t)tb * Cd + i];

    float acc[4][8][4];
#pragma unroll
    for (int i = 0; i < 4; i++)
#pragma unroll
        for (int j = 0; j < 8; j++)
#pragma unroll
            for (int r = 0; r < 4; r++) acc[i][j][r] = 0.f;

    auto issue = [&](int ch) {
        const uint32_t stg = sb + (ch & 3) * STG_P;
        const int k0 = ch * 32;
#pragma unroll
        for (int it = 0; it < 2; it++) {          // A: 512 cp16
            int o = tid + it * 256;
            int r = o >> 2, cq = o & 3;
            cp16(stg + r * 80 + cq * 16, &g_w[0][row_off + m_blk + r][k0 + cq * 8]);
        }
#pragma unroll
        for (int it = 0; it < 4; it++) {          // B: 1024 cp16
            int o = tid + it * 256;
            int r = o >> 5, q = o & 31;
            cp16(stg + ASTG_P + r * 528 + q * 16,
                 &Bmat[(size_t)(k0 + r) * NTOT + n_blk + q * 8]);
        }
        cp_commit();
    };

    auto compute = [&](int ch) {
        const uint32_t stg = sb + (ch & 3) * STG_P;
        const int k0 = ch * 32;
#pragma unroll
        for (int ks = 0; ks < 2; ks++) {
            const int kk = ks * 16;
            uint32_t bfrag[8][2];
#pragma unroll
            for (int h = 0; h < 4; h++) {
                uint32_t r0, r1, r2, r3;
                uint32_t a = stg + ASTG_P + (kk + (lane & 15)) * 528
                           + (wn0 + h * 16 + (lane >> 4) * 8) * 2;
                ldsm_x4t(r0, r1, r2, r3, a);
                bfrag[h * 2][0] = r0;     bfrag[h * 2][1] = r1;
                bfrag[h * 2 + 1][0] = r2; bfrag[h * 2 + 1][1] = r3;
            }
            uint32_t kvlo = *(const uint32_t*)&skv[k0 + kk + (lane & 3) * 2];
            uint32_t kvhi = *(const uint32_t*)&skv[k0 + kk + 8 + (lane & 3) * 2];
            __half2 lo = *(__half2*)&kvlo, hi = *(__half2*)&kvhi;
            uint32_t afr[4][4];
#pragma unroll
            for (int mt = 0; mt < 4; mt++) {
                ldsm_x4(afr[mt],
                        stg + (wm0 + mt * 16 + (lane & 15)) * 80
                        + (kk + (lane >> 4) * 8) * 2);
                __half2* af = (__half2*)afr[mt];
                af[0] = __hmul2(af[0], lo); af[1] = __hmul2(af[1], lo);
                af[2] = __hmul2(af[2], hi); af[3] = __hmul2(af[3], hi);
            }
#pragma unroll
            for (int mt = 0; mt < 4; mt++)
#pragma unroll
                for (int nt = 0; nt < 8; nt++)
                    mma_f16(acc[mt][nt], afr[mt], bfrag[nt]);
        }
    };

    issue(0); issue(1); issue(2);
#pragma unroll
    for (int ch = 0; ch < 12; ch++) {
        int rem = 11 - ch;
        if (rem >= 2) cp_wait<2>(); else if (rem == 1) cp_wait<1>(); else cp_wait<0>();
        __syncthreads();
        if (ch + 3 < 12) issue(ch + 3);
        compute(ch);
    }

    const int g = lane >> 2, tig = lane & 3;
#pragma unroll
    for (int mt = 0; mt < 4; mt++) {
#pragma unroll
        for (int i = 0; i < 2; i++) {
            int row = m_blk + wm0 + mt * 16 + g + i * 8;
            float sc = g_scale[row_off + row] * WSCI;
            float bi = g_bias[row_off + row];
#pragma unroll
            for (int nt = 0; nt < 8; nt++) {
#pragma unroll
                for (int j = 0; j < 2; j++) {
                    int n = wn0 + nt * 8 + tig * 2 + j;
                    float val = acc[mt][nt][i * 2 + j] * sc + bi;
                    size_t oi = ((size_t)tb * Cd + row) * HWd + n;
                    out[oi] = val + identity[oi];
                }
            }
        }
    }
}

// ---------------------------------------------------------------------------
// kv = lif( sum_n k*v , v_th=0.5 ): block per (b,c), 128 threads, half2 loads
// ---------------------------------------------------------------------------
__global__ void kv_kernel()
{
    int bc = blockIdx.x;
    int c = bc % Cd, b = bc / Cd;
    int i = threadIdx.x;                           // 0..127, n = 2i, 2i+1
    float p[Td];
#pragma unroll
    for (int t = 0; t < Td; t++) {
        size_t o = (size_t)(t * Bd + b) * HWd + 2 * i;
        __half2 kk = *(const __half2*)&g_sqkv[(size_t)(Cd + c) * NTOT + o];
        __half2 vv = *(const __half2*)&g_sqkv[(size_t)(2 * Cd + c) * NTOT + o];
        __half2 pr = __hmul2(kk, vv);
        p[t] = __low2float(pr) + __high2float(pr);
    }
#pragma unroll
    for (int t = 0; t < Td; t++)
        for (int o = 16; o > 0; o >>= 1) p[t] += __shfl_down_sync(0xffffffffu, p[t], o);
    __shared__ float wsum[Td][4];
    int lane = i & 31, wid = i >> 5;
    if (lane == 0)
#pragma unroll
        for (int t = 0; t < Td; t++) wsum[t][wid] = p[t];
    __syncthreads();
    if (i == 0) {
        float v = 0.f;
#pragma unroll
        for (int t = 0; t < Td; t++) {
            float kvp = wsum[t][0] + wsum[t][1] + wsum[t][2] + wsum[t][3];
            v = 0.5f * (v + kvp);
            float s = (v >= 0.5f) ? 1.f : 0.f;
            v *= (1.f - s);
            g_kvs[(size_t)(t * Bd + b) * Cd + c] = __float2half(s);
        }
    }
}

// ---------------------------------------------------------------------------
__global__ void vout_kernel(float* __restrict__ out2)
{
    __shared__ __half s[CHD][HWd + 8];
    int tb = blockIdx.x, head = blockIdx.y;
    int tid = threadIdx.x;                    // 256
#pragma unroll
    for (int ch = 0; ch < CHD; ch++)
        s[ch][tid] = g_sqkv[(size_t)(2 * Cd + head * CHD + ch) * NTOT
                            + (size_t)tb * HWd + tid];
    __syncthreads();
#pragma unroll
    for (int it = 0; it < CHD; it++) {
        int idx = it * 256 + tid;             // 48*256 elems, contiguous out
        int ch = idx % CHD, n = idx / CHD;
        out2[((size_t)(tb * HEADS + head) * HWd + n) * CHD + ch] =
            __half2float(s[ch][n]);
    }
}

// ---------------------------------------------------------------------------
// side-stream resources: created once on the FIRST (uncaptured) call
struct SideRes {
    cudaStream_t s;
    cudaEvent_t e0, eW, e1, eV;
    SideRes() {
        cudaStreamCreateWithFlags(&s, cudaStreamNonBlocking);
        cudaEventCreateWithFlags(&e0, cudaEventDisableTiming);
        cudaEventCreateWithFlags(&eW, cudaEventDisableTiming);
        cudaEventCreateWithFlags(&e1, cudaEventDisableTiming);
        cudaEventCreateWithFlags(&eV, cudaEventDisableTiming);
    }
};

extern "C" void kernel_launch(void* const* d_in, const int* in_sizes, int n_in,
                              void* d_out, int out_size)
{
    const float* x   = (const float*)d_in[0];
    const float* qw  = (const float*)d_in[1];
    const float* qg  = (const float*)d_in[2];
    const float* qb  = (const float*)d_in[3];
    const float* qm  = (const float*)d_in[4];
    const float* qv  = (const float*)d_in[5];
    const float* kw  = (const float*)d_in[6];
    const float* kg  = (const float*)d_in[7];
    const float* kb  = (const float*)d_in[8];
    const float* km  = (const float*)d_in[9];
    const float* kv  = (const float*)d_in[10];
    const float* vw  = (const float*)d_in[11];
    const float* vg  = (const float*)d_in[12];
    const float* vb  = (const float*)d_in[13];
    const float* vm  = (const float*)d_in[14];
    const float* vv  = (const float*)d_in[15];
    const float* pw  = (const float*)d_in[16];
    const float* pb  = (const float*)d_in[17];
    const float* pg  = (const float*)d_in[18];
    const float* pbe = (const float*)d_in[19];
    const float* pm  = (const float*)d_in[20];
    const float* pv  = (const float*)d_in[21];

    static SideRes R;           // constructed on the uncaptured correctness call

    cudaFuncSetAttribute(mma_gemm_qkv, cudaFuncAttributeMaxDynamicSharedMemorySize, DSMEM);
    cudaFuncSetAttribute(mma_gemm_proj, cudaFuncAttributeMaxDynamicSharedMemorySize, DSMEM_P);

    __half *p_sx, *p_sq;
    cudaGetSymbolAddress((void**)&p_sx, g_sx);
    cudaGetSymbolAddress((void**)&p_sq, g_sqkv);

    float* out = (float*)d_out;

    // fork 1: weight split on side stream, lif_x on main
    cudaEventRecord(R.e0, 0);
    cudaStreamWaitEvent(R.s, R.e0, 0);
    wsplit_prep_kernel<<<2305, 256, 0, R.s>>>(qw, kw, vw, pw,
                                              qg, qb, qm, qv, kg, kb, km, kv,
                                              vg, vb, vm, vv, pb, pg, pbe, pm, pv);
    cudaEventRecord(R.eW, R.s);

    lif_x_kernel<<<12288, 256>>>(x);
    cudaStreamWaitEvent(0, R.eW, 0);               // join before qkv

    dim3 g1(Bd * 4, 9);                            // full qkv, single launch
    mma_gemm_qkv<<<g1, 256, DSMEM>>>(p_sx);

    // fork 2: vout on side (runs through kv AND proj), kv+proj on main
    cudaEventRecord(R.e1, 0);
    cudaStreamWaitEvent(R.s, R.e1, 0);
    if (out_size >= 2 * NELEM)
        vout_kernel<<<dim3(Td * Bd, HEADS), 256, 0, R.s>>>(out + NELEM);
    cudaEventRecord(R.eV, R.s);

    kv_kernel<<<Bd * Cd, 128>>>();

    dim3 g2(Td * Bd, 3);                           // 128 tb x 3 row-tiles
    mma_gemm_proj<<<g2, 256, DSMEM_P>>>(p_sq, out, x);

    cudaStreamWaitEvent(0, R.eV, 0);               // final join: vout done
}